// round 10
// baseline (speedup 1.0000x reference)
#include <cuda_runtime.h>
#include <cuda_bf16.h>

// PropagationOnly_SharedPixel: 12 iterations of
//   u <- tanh(scalar * (const + w[i] * sum_{3x3}(u)))
// on a 64x64 grid, batch 128. 9-point box stencil (hiddenWeight unused).
//
// R10: 256 threads, warp = 8 rows, lane = 2 adjacent cols -> 16 px/thread.
// 6 of 8 rows are interior (register-only stencil) computed before the halo
// LDS so they overlap the deferred-blocking barrier; only rows 0,7 touch
// SMEM. f32x2 packed math, 4-wide shared-rcp tanh, double buffer, one
// __syncthreads per iteration (R8/R9 showed pairwise/split barriers don't
// beat it).

#define NSIDE 64
#define HPIX  4096
#define ITERS 12
#define SROWS 18           // 16 stored boundary rows + zero row above/below

__device__ __forceinline__ float ex2_approx(float x) {
    float y; asm("ex2.approx.f32 %0, %1;" : "=f"(y) : "f"(x)); return y;
}
__device__ __forceinline__ float rcp_approx(float x) {
    float y; asm("rcp.approx.f32 %0, %1;" : "=f"(y) : "f"(x)); return y;
}
__device__ __forceinline__ float2 add2(float2 a, float2 b) {
    unsigned long long ua, ub, ur;
    ua = *reinterpret_cast<unsigned long long*>(&a);
    ub = *reinterpret_cast<unsigned long long*>(&b);
    asm("add.rn.f32x2 %0, %1, %2;" : "=l"(ur) : "l"(ua), "l"(ub));
    return *reinterpret_cast<float2*>(&ur);
}
__device__ __forceinline__ float2 fma2(float2 a, float2 b, float2 c) {
    unsigned long long ua, ub, uc, ur;
    ua = *reinterpret_cast<unsigned long long*>(&a);
    ub = *reinterpret_cast<unsigned long long*>(&b);
    uc = *reinterpret_cast<unsigned long long*>(&c);
    asm("fma.rn.f32x2 %0, %1, %2, %3;" : "=l"(ur) : "l"(ua), "l"(ub), "l"(uc));
    return *reinterpret_cast<float2*>(&ur);
}

struct Pair { float2 lo, hi; };

// tanh for 4 pixels (two packed pairs) with ONE rcp:
// 1/d_i reconstructed from prefix/suffix products around rcp(d0*d1*d2*d3).
__device__ __forceinline__ Pair tanh4(float2 ta, float2 tb,
                                      float2 mneg2, float2 one2)
{
    const float a0 = fminf(ta.x, 24.0f), a1 = fminf(ta.y, 24.0f);
    const float b0 = fminf(tb.x, 24.0f), b1 = fminf(tb.y, 24.0f);
    const float dA0 = 1.0f + ex2_approx(a0);
    const float dA1 = 1.0f + ex2_approx(a1);
    const float dB0 = 1.0f + ex2_approx(b0);
    const float dB1 = 1.0f + ex2_approx(b1);
    const float pA = dA0 * dA1;                 // <= 2^50, finite
    const float pB = dB0 * dB1;
    const float R  = rcp_approx(pA * pB);       // <= 2^100, finite
    const float RA = R * pB;                    // = 1/pA
    const float RB = R * pA;                    // = 1/pB
    float2 iA, iB;
    iA.x = RA * dA1;  iA.y = RA * dA0;          // 1/dA0, 1/dA1
    iB.x = RB * dB1;  iB.y = RB * dB0;
    Pair r;
    r.lo = fma2(mneg2, iA, one2);               // tanh = 1 - 2/d
    r.hi = fma2(mneg2, iB, one2);
    return r;
}

__global__ void __launch_bounds__(256, 1)
prop_stencil_kernel(const float* __restrict__ X,
                    const float* __restrict__ pred,
                    const float* __restrict__ w,
                    const float* __restrict__ a,
                    const float* __restrict__ bias,
                    const float* __restrict__ scalar_p,
                    float* __restrict__ out)
{
    __shared__ float buf[2][SROWS][NSIDE];      // 2 x 18 x 64 x 4 = 9.2 KB

    const int b    = blockIdx.x;
    const int tid  = threadIdx.x;
    const int wid  = tid >> 5;                  // 0..7 -> rows 8w..8w+7
    const int lane = tid & 31;                  // -> cols 2l, 2l+1
    const int r0   = wid << 3;
    const int c0   = lane << 1;

    // Zero rows 0 and 17 of both buffers: 256 words, one per thread.
    {
        const int bb = tid >> 7;
        const int rr = ((tid >> 6) & 1) ? (SROWS - 1) : 0;
        buf[bb][rr][tid & 63] = 0.0f;
    }

    const float K = scalar_p[0] * 2.88539008177793f;   // 2*scalar*log2(e)

    const float2* Xb = (const float2*)(X    + (size_t)b * HPIX);
    const float2* Pb = (const float2*)(pred + (size_t)b * HPIX);
    const float2* w2 = (const float2*)w;
    const float2* a2 = (const float2*)a;
    const float2* b2 = (const float2*)bias;

    // 16 pixels per thread, packed: u[row].{x,y} = cols c0, c0+1.
    float2 u[8], cs[8], wk[8];
    #pragma unroll
    for (int k = 0; k < 8; k++) {
        const int i = (r0 + k) * 32 + lane;
        const float2 p  = Pb[i];
        const float2 x  = Xb[i];
        const float2 ww = w2[i];
        const float2 aa = a2[i];
        const float2 bs = b2[i];
        u[k] = p;
        cs[k].x = (((p.x == -1.0f) ? 0.0f : p.x) + bs.x + aa.x * x.x) * K;
        cs[k].y = (((p.y == -1.0f) ? 0.0f : p.y) + bs.y + aa.y * x.y) * K;
        wk[k].x = ww.x * K;  wk[k].y = ww.y * K;
    }

    // Border masks packed: s = {VL,VR}*{zL,zR} + {h,h}.
    const float2 zLR   = make_float2((lane == 0) ? 0.0f : 1.0f,
                                     (lane == 31) ? 0.0f : 1.0f);
    const float2 mneg2 = make_float2(-2.0f, -2.0f);
    const float2 one2  = make_float2( 1.0f,  1.0f);

    // Seed buffer 0's boundary rows: warp w stores row 8w -> slot 2w+1,
    // row 8w+7 -> slot 2w+2; reads top halo (8w-1) from slot 2w, bottom halo
    // (8w+8) from slot 2w+3; slots 0 and 17 are the zero border.
    *(float2*)&buf[0][2 * wid + 1][c0] = u[0];
    *(float2*)&buf[0][2 * wid + 2][c0] = u[7];
    __syncthreads();        // covers zero-fill + seeding, once.

    #pragma unroll
    for (int it = 0; it < ITERS; it++) {
        const float (*S)[NSIDE] = buf[it & 1];

        // ---- Phase 1: interior rows 1..6 — register-only stencil; issues
        // past the (deferred-blocking) barrier while other warps arrive. ----
        float2 m[7];
        #pragma unroll
        for (int r = 0; r < 7; r++) m[r] = add2(u[r], u[r + 1]);

        float2 t[8];
        #pragma unroll
        for (int r = 1; r <= 6; r++) {
            const float2 V = add2(m[r - 1], u[r + 1]);    // rows r-1+r+r+1
            const float VL = __shfl_up_sync(0xffffffffu, V.y, 1);
            const float VR = __shfl_down_sync(0xffffffffu, V.x, 1);
            const float h  = V.x + V.y;
            const float2 s = fma2(make_float2(VL, VR), zLR, make_float2(h, h));
            t[r] = fma2(wk[r], s, cs[r]);
        }
        const Pair n12 = tanh4(t[1], t[2], mneg2, one2);
        const Pair n34 = tanh4(t[3], t[4], mneg2, one2);
        const Pair n56 = tanh4(t[5], t[6], mneg2, one2);

        // ---- Phase 2: boundary rows 0,7 — consume neighbors' halo. ----
        const float2 top = *(const float2*)&S[2 * wid    ][c0];  // row 8w-1
        const float2 bot = *(const float2*)&S[2 * wid + 3][c0];  // row 8w+8
        {
            const float2 V0 = add2(top, m[0]);
            const float2 V7 = add2(m[6], bot);
            const float VL0 = __shfl_up_sync(0xffffffffu, V0.y, 1);
            const float VR0 = __shfl_down_sync(0xffffffffu, V0.x, 1);
            const float VL7 = __shfl_up_sync(0xffffffffu, V7.y, 1);
            const float VR7 = __shfl_down_sync(0xffffffffu, V7.x, 1);
            const float h0 = V0.x + V0.y;
            const float h7 = V7.x + V7.y;
            const float2 s0 = fma2(make_float2(VL0, VR0), zLR, make_float2(h0, h0));
            const float2 s7 = fma2(make_float2(VL7, VR7), zLR, make_float2(h7, h7));
            t[0] = fma2(wk[0], s0, cs[0]);
            t[7] = fma2(wk[7], s7, cs[7]);
        }
        const Pair n07 = tanh4(t[0], t[7], mneg2, one2);
        u[0] = n07.lo;  u[7] = n07.hi;

        if (it < ITERS - 1) {
            float (*D)[NSIDE] = buf[(it + 1) & 1];
            *(float2*)&D[2 * wid + 1][c0] = u[0];
            *(float2*)&D[2 * wid + 2][c0] = u[7];
            __syncthreads();    // single barrier per iteration (double buffer);
                                // next iter's phase 1 issues past it
                                // (deferred-blocking), blocking only at LDS.
        }

        u[1] = n12.lo;  u[2] = n12.hi;
        u[3] = n34.lo;  u[4] = n34.hi;
        u[5] = n56.lo;  u[6] = n56.hi;
    }

    // Final values straight from registers (packed stores).
    float2* ob = (float2*)(out + (size_t)b * HPIX);
    #pragma unroll
    for (int k = 0; k < 8; k++)
        ob[(r0 + k) * 32 + lane] = u[k];
}

extern "C" void kernel_launch(void* const* d_in, const int* in_sizes, int n_in,
                              void* d_out, int out_size)
{
    const float* X      = (const float*)d_in[0];  // [B,4096]
    const float* pred   = (const float*)d_in[1];  // [B,4096]
    const float* w      = (const float*)d_in[2];  // [4096]
    const float* a      = (const float*)d_in[3];  // [4096]
    const float* bias   = (const float*)d_in[4];  // [4096]
    const float* scalar = (const float*)d_in[5];  // [1]
    // d_in[6] = hiddenWeight (unused: fixed 3x3 grid adjacency), d_in[7] = dtype
    float* out = (float*)d_out;

    const int B = in_sizes[0] / HPIX;             // 128
    prop_stencil_kernel<<<B, 256>>>(X, pred, w, a, bias, scalar, out);
}